// round 1
// baseline (speedup 1.0000x reference)
#include <cuda_runtime.h>
#include <stdint.h>

#define BB 64
#define CC 3
#define JJ 11
#define TT 512
#define CO 128
#define NPTS (BB*JJ*TT)      /* 360448 = 256*1408 = 128*2816 */
#define SIGC 84
#define K1D 168              /* sig channels (spatial 84 + temporal 84) */
#define K2D 256              /* fus input channels */
#define RCHUNKS 64

// ---------------- static scratch (no allocations allowed) ----------------
__device__ float g_S[K1D * NPTS];        // sig, layout [k][p]
__device__ float g_U[CO * NPTS];         // raw-conv pre-BN, [o][p]
__device__ float g_V[CO * NPTS];         // ps-conv  pre-BN, [o][p]
__device__ float g_F[CO * NPTS];         // fus-conv pre-BN, [o][p]
__device__ float g_pS[K2D * RCHUNKS];    // partial sums (U: 0..127, V: 128..255)
__device__ float g_pQ[K2D * RCHUNKS];
__device__ float g_pS2[CO * RCHUNKS];    // partial sums for F
__device__ float g_pQ2[CO * RCHUNKS];
__device__ float g_sc1[K2D], g_bi1[K2D]; // BN affine for U(0..127)/V(128..255)
__device__ float g_sc2[CO],  g_bi2[CO];  // BN affine for F

// ---------------- depth-3 signature Chen step (c = 4) ----------------
__device__ __forceinline__ void sig_step(float S1[4], float S2[16], float S3[64],
                                         const float d[4]) {
    float dd[16];
#pragma unroll
    for (int i = 0; i < 4; i++)
#pragma unroll
        for (int j = 0; j < 4; j++) dd[i*4+j] = d[i]*d[j];
    float a[4];
#pragma unroll
    for (int i = 0; i < 4; i++) a[i] = 0.5f*S1[i] + d[i]*(1.0f/6.0f);
    // S3 += S2 (x) d + S1 (x) (0.5 d(x)d) + d(x)d(x)d/6
#pragma unroll
    for (int i = 0; i < 4; i++)
#pragma unroll
        for (int j = 0; j < 4; j++)
#pragma unroll
            for (int k = 0; k < 4; k++)
                S3[i*16+j*4+k] += S2[i*4+j]*d[k] + a[i]*dd[j*4+k];
#pragma unroll
    for (int i = 0; i < 4; i++)
#pragma unroll
        for (int j = 0; j < 4; j++)
            S2[i*4+j] += S1[i]*d[j] + 0.5f*dd[i*4+j];
#pragma unroll
    for (int i = 0; i < 4; i++) S1[i] += d[i];
}

__device__ __forceinline__ void sig_write(int rowbase, int p,
                                          const float S1[4], const float S2[16],
                                          const float S3[64]) {
#pragma unroll
    for (int i = 0; i < 4; i++)  g_S[(rowbase + i)      * NPTS + p] = S1[i];
#pragma unroll
    for (int i = 0; i < 16; i++) g_S[(rowbase + 4 + i)  * NPTS + p] = S2[i];
#pragma unroll
    for (int i = 0; i < 64; i++) g_S[(rowbase + 20 + i) * NPTS + p] = S3[i];
}

// ---------------- K1: per-point spatial + temporal signatures ----------------
__global__ void k_sig(const float* __restrict__ x, const int* __restrict__ path) {
    int p = blockIdx.x * blockDim.x + threadIdx.x;
    if (p >= NPTS) return;
    int t  = p & (TT - 1);
    int bj = p >> 9;
    int j  = bj % JJ;
    int b  = bj / JJ;
    const float* xb = x + (size_t)b * CC * JJ * TT;

    float S1[4], S2[16], S3[64];
    float prev[3], cur[3], d[4];

    // ---- spatial: L=3, time increments 0, 0.5, 0.5 ----
#pragma unroll
    for (int i = 0; i < 4; i++)  S1[i] = 0.f;
#pragma unroll
    for (int i = 0; i < 16; i++) S2[i] = 0.f;
#pragma unroll
    for (int i = 0; i < 64; i++) S3[i] = 0.f;

    int j0 = path[j*3+0], j1 = path[j*3+1], j2 = path[j*3+2];
#pragma unroll
    for (int c = 0; c < 3; c++) prev[c] = xb[(c*JJ + j0)*TT + t];
    d[0] = 0.f; d[1] = prev[0]; d[2] = prev[1]; d[3] = prev[2];
    sig_step(S1, S2, S3, d);
#pragma unroll
    for (int c = 0; c < 3; c++) cur[c] = xb[(c*JJ + j1)*TT + t];
    d[0] = 0.5f;
#pragma unroll
    for (int c = 0; c < 3; c++) { d[c+1] = cur[c] - prev[c]; prev[c] = cur[c]; }
    sig_step(S1, S2, S3, d);
#pragma unroll
    for (int c = 0; c < 3; c++) cur[c] = xb[(c*JJ + j2)*TT + t];
    d[0] = 0.5f;
#pragma unroll
    for (int c = 0; c < 3; c++) d[c+1] = cur[c] - prev[c];
    sig_step(S1, S2, S3, d);
    sig_write(0, p, S1, S2, S3);

    // ---- temporal: L=7, edge-clamped window, time increments 0 then 1/6 ----
#pragma unroll
    for (int i = 0; i < 4; i++)  S1[i] = 0.f;
#pragma unroll
    for (int i = 0; i < 16; i++) S2[i] = 0.f;
#pragma unroll
    for (int i = 0; i < 64; i++) S3[i] = 0.f;

#pragma unroll
    for (int l = 0; l < 7; l++) {
        int tc = t + l - 3;
        tc = tc < 0 ? 0 : (tc > TT-1 ? TT-1 : tc);
#pragma unroll
        for (int c = 0; c < 3; c++) cur[c] = xb[(c*JJ + j)*TT + tc];
        if (l == 0) {
            d[0] = 0.f;
#pragma unroll
            for (int c = 0; c < 3; c++) d[c+1] = cur[c];
        } else {
            d[0] = 1.0f/6.0f;
#pragma unroll
            for (int c = 0; c < 3; c++) d[c+1] = cur[c] - prev[c];
        }
#pragma unroll
        for (int c = 0; c < 3; c++) prev[c] = cur[c];
        sig_step(S1, S2, S3, d);
    }
    sig_write(SIGC, p, S1, S2, S3);
}

// ---------------- K2: raw (1x3) conv + bias -> g_U ----------------
__global__ void k_raw(const float* __restrict__ x, const float* __restrict__ w,
                      const float* __restrict__ b) {
    __shared__ float xs[3][TT + 2];
    __shared__ float ws[CO * 9];
    __shared__ float bs[CO];
    int bj = blockIdx.x;
    int j = bj % JJ, bb = bj / JJ;
    int tid = threadIdx.x;

    for (int i = tid; i < 3*(TT+2); i += 256) {
        int c = i / (TT+2), tt = i % (TT+2);
        xs[c][tt] = (tt >= 1 && tt <= TT) ? x[((bb*3 + c)*JJ + j)*TT + tt - 1] : 0.f;
    }
    for (int i = tid; i < CO*9; i += 256) ws[i] = w[i];
    if (tid < CO) bs[tid] = b[tid];
    __syncthreads();

    int t0 = tid, t1 = 256 + tid;
    float xv0[3][3], xv1[3][3];
#pragma unroll
    for (int c = 0; c < 3; c++)
#pragma unroll
        for (int kw = 0; kw < 3; kw++) {
            xv0[c][kw] = xs[c][t0 + kw];
            xv1[c][kw] = xs[c][t1 + kw];
        }
    int pbase = bj * TT;
    for (int o = 0; o < CO; o++) {
        float a0 = bs[o], a1 = bs[o];
#pragma unroll
        for (int c = 0; c < 3; c++)
#pragma unroll
            for (int kw = 0; kw < 3; kw++) {
                float wv = ws[o*9 + c*3 + kw];
                a0 = fmaf(xv0[c][kw], wv, a0);
                a1 = fmaf(xv1[c][kw], wv, a1);
            }
        g_U[(size_t)o*NPTS + pbase + t0] = a0;
        g_U[(size_t)o*NPTS + pbase + t1] = a1;
    }
}

// ---------------- K3: ps GEMM  V[o][p] = ps_w[o][k] * S[k][p] + ps_b ----------------
__global__ void __launch_bounds__(256, 2) k_gemm_ps(const float* __restrict__ W,
                                                    const float* __restrict__ bias) {
    __shared__ float As[8][128];
    __shared__ float Bs[8][128];
    int tid = threadIdx.x;
    int tr = tid >> 4, tc = tid & 15;
    int m0 = blockIdx.x * 128;
    int la_k = tid >> 5;            // 0..7
    int la_m = (tid & 31) << 2;     // 0..124
    int lb_n = tid >> 1;            // 0..127
    int lb_k = (tid & 1) << 2;      // 0 or 4

    float acc[8][8];
#pragma unroll
    for (int i = 0; i < 8; i++)
#pragma unroll
        for (int jn = 0; jn < 8; jn++) acc[i][jn] = 0.f;

    for (int k0 = 0; k0 < K1D; k0 += 8) {
        float4 av = *(const float4*)(&g_S[(size_t)(k0 + la_k)*NPTS + m0 + la_m]);
        *(float4*)&As[la_k][la_m] = av;
        float4 bv = *(const float4*)(&W[lb_n*K1D + k0 + lb_k]);
        Bs[lb_k+0][lb_n] = bv.x; Bs[lb_k+1][lb_n] = bv.y;
        Bs[lb_k+2][lb_n] = bv.z; Bs[lb_k+3][lb_n] = bv.w;
        __syncthreads();
#pragma unroll
        for (int kk = 0; kk < 8; kk++) {
            float ra[8], rb[8];
            *(float4*)(ra)   = *(const float4*)&As[kk][tr*8];
            *(float4*)(ra+4) = *(const float4*)&As[kk][tr*8+4];
            *(float4*)(rb)   = *(const float4*)&Bs[kk][tc*8];
            *(float4*)(rb+4) = *(const float4*)&Bs[kk][tc*8+4];
#pragma unroll
            for (int i = 0; i < 8; i++)
#pragma unroll
                for (int jn = 0; jn < 8; jn++)
                    acc[i][jn] = fmaf(ra[i], rb[jn], acc[i][jn]);
        }
        __syncthreads();
    }
#pragma unroll
    for (int jn = 0; jn < 8; jn++) {
        int n = tc*8 + jn;
        float bn_ = bias[n];
        float* dst = &g_V[(size_t)n*NPTS + m0 + tr*8];
        float4 v0 = {acc[0][jn]+bn_, acc[1][jn]+bn_, acc[2][jn]+bn_, acc[3][jn]+bn_};
        float4 v1 = {acc[4][jn]+bn_, acc[5][jn]+bn_, acc[6][jn]+bn_, acc[7][jn]+bn_};
        *(float4*)dst = v0; *(float4*)(dst+4) = v1;
    }
}

// ---------------- K5: fus GEMM over BN+ReLU'd [U;V] ----------------
__global__ void __launch_bounds__(256, 2) k_gemm_fus(const float* __restrict__ W,
                                                     const float* __restrict__ bias) {
    __shared__ float As[8][128];
    __shared__ float Bs[8][128];
    __shared__ float ssc[K2D], sbi[K2D];
    int tid = threadIdx.x;
    for (int i = tid; i < K2D; i += 256) { ssc[i] = g_sc1[i]; sbi[i] = g_bi1[i]; }
    __syncthreads();

    int tr = tid >> 4, tc = tid & 15;
    int m0 = blockIdx.x * 128;
    int la_k = tid >> 5;
    int la_m = (tid & 31) << 2;
    int lb_n = tid >> 1;
    int lb_k = (tid & 1) << 2;

    float acc[8][8];
#pragma unroll
    for (int i = 0; i < 8; i++)
#pragma unroll
        for (int jn = 0; jn < 8; jn++) acc[i][jn] = 0.f;

    for (int k0 = 0; k0 < K2D; k0 += 8) {
        int kg = k0 + la_k;
        const float* src = (kg < CO) ? &g_U[(size_t)kg*NPTS] : &g_V[(size_t)(kg - CO)*NPTS];
        float4 av = *(const float4*)(src + m0 + la_m);
        float sc = ssc[kg], bi = sbi[kg];
        av.x = fmaxf(fmaf(av.x, sc, bi), 0.f);
        av.y = fmaxf(fmaf(av.y, sc, bi), 0.f);
        av.z = fmaxf(fmaf(av.z, sc, bi), 0.f);
        av.w = fmaxf(fmaf(av.w, sc, bi), 0.f);
        *(float4*)&As[la_k][la_m] = av;
        float4 bv = *(const float4*)(&W[lb_n*K2D + k0 + lb_k]);
        Bs[lb_k+0][lb_n] = bv.x; Bs[lb_k+1][lb_n] = bv.y;
        Bs[lb_k+2][lb_n] = bv.z; Bs[lb_k+3][lb_n] = bv.w;
        __syncthreads();
#pragma unroll
        for (int kk = 0; kk < 8; kk++) {
            float ra[8], rb[8];
            *(float4*)(ra)   = *(const float4*)&As[kk][tr*8];
            *(float4*)(ra+4) = *(const float4*)&As[kk][tr*8+4];
            *(float4*)(rb)   = *(const float4*)&Bs[kk][tc*8];
            *(float4*)(rb+4) = *(const float4*)&Bs[kk][tc*8+4];
#pragma unroll
            for (int i = 0; i < 8; i++)
#pragma unroll
                for (int jn = 0; jn < 8; jn++)
                    acc[i][jn] = fmaf(ra[i], rb[jn], acc[i][jn]);
        }
        __syncthreads();
    }
#pragma unroll
    for (int jn = 0; jn < 8; jn++) {
        int n = tc*8 + jn;
        float bn_ = bias[n];
        float* dst = &g_F[(size_t)n*NPTS + m0 + tr*8];
        float4 v0 = {acc[0][jn]+bn_, acc[1][jn]+bn_, acc[2][jn]+bn_, acc[3][jn]+bn_};
        float4 v1 = {acc[4][jn]+bn_, acc[5][jn]+bn_, acc[6][jn]+bn_, acc[7][jn]+bn_};
        *(float4*)dst = v0; *(float4*)(dst+4) = v1;
    }
}

// ---------------- deterministic two-stage BN reduction ----------------
__global__ void k_reduce(int which) {
    int c = blockIdx.y, chunk = blockIdx.x;
    const float* src; float* pS; float* pQ;
    if (which == 0)      { src = g_U; pS = g_pS;                pQ = g_pQ; }
    else if (which == 1) { src = g_V; pS = g_pS + CO*RCHUNKS;   pQ = g_pQ + CO*RCHUNKS; }
    else                 { src = g_F; pS = g_pS2;               pQ = g_pQ2; }
    const float* row = src + (size_t)c * NPTS;
    float s = 0.f, q = 0.f;
    for (int i = chunk*256 + threadIdx.x; i < NPTS; i += RCHUNKS*256) {
        float v = row[i]; s += v; q += v*v;
    }
    __shared__ float sh[512];
    sh[threadIdx.x] = s; sh[256 + threadIdx.x] = q;
    __syncthreads();
    for (int st = 128; st; st >>= 1) {
        if (threadIdx.x < st) {
            sh[threadIdx.x]       += sh[threadIdx.x + st];
            sh[256 + threadIdx.x] += sh[256 + threadIdx.x + st];
        }
        __syncthreads();
    }
    if (threadIdx.x == 0) {
        pS[c*RCHUNKS + chunk] = sh[0];
        pQ[c*RCHUNKS + chunk] = sh[256];
    }
}

__global__ void k_fin1(const float* __restrict__ rg, const float* __restrict__ rb,
                       const float* __restrict__ pg, const float* __restrict__ pb) {
    int c = threadIdx.x;  // 256
    float s = 0.f, q = 0.f;
    for (int i = 0; i < RCHUNKS; i++) { s += g_pS[c*RCHUNKS+i]; q += g_pQ[c*RCHUNKS+i]; }
    float mean = s / (float)NPTS;
    float var  = q / (float)NPTS - mean*mean;
    float rstd = rsqrtf(var + 1e-5f);
    float g  = (c < CO) ? rg[c] : pg[c - CO];
    float be = (c < CO) ? rb[c] : pb[c - CO];
    g_sc1[c] = rstd * g;
    g_bi1[c] = be - mean * rstd * g;
}

__global__ void k_fin2(const float* __restrict__ fg, const float* __restrict__ fb) {
    int c = threadIdx.x;  // 128
    float s = 0.f, q = 0.f;
    for (int i = 0; i < RCHUNKS; i++) { s += g_pS2[c*RCHUNKS+i]; q += g_pQ2[c*RCHUNKS+i]; }
    float mean = s / (float)NPTS;
    float var  = q / (float)NPTS - mean*mean;
    float rstd = rsqrtf(var + 1e-5f);
    g_sc2[c] = rstd * fg[c];
    g_bi2[c] = fb[c] - mean * rstd * fg[c];
}

// ---------------- K7: affine + relu + layout transform -> out ----------------
__global__ void k_out(float* __restrict__ out) {
    int e = blockIdx.x * 256 + threadIdx.x;   // < CO*NPTS (fits int)
    int o = e / NPTS;                          // constant per block (NPTS % 256 == 0)
    int p = e - o * NPTS;
    int t  = p & (TT - 1);
    int bj = p >> 9;
    int j  = bj % JJ;
    int b  = bj / JJ;
    float v = fmaf(g_F[e], g_sc2[o], g_bi2[o]);
    out[((b*CO + o)*JJ + j)*TT + t] = fmaxf(v, 0.f);
}

// ---------------- launcher ----------------
extern "C" void kernel_launch(void* const* d_in, const int* in_sizes, int n_in,
                              void* d_out, int out_size) {
    const float* x      = (const float*)d_in[0];
    const int*   path   = (const int*)  d_in[1];
    const float* raw_w  = (const float*)d_in[2];
    const float* raw_b  = (const float*)d_in[3];
    const float* raw_g  = (const float*)d_in[4];
    const float* raw_be = (const float*)d_in[5];
    const float* ps_w   = (const float*)d_in[6];
    const float* ps_b   = (const float*)d_in[7];
    const float* ps_g   = (const float*)d_in[8];
    const float* ps_be  = (const float*)d_in[9];
    const float* fus_w  = (const float*)d_in[10];
    const float* fus_b  = (const float*)d_in[11];
    const float* fus_g  = (const float*)d_in[12];
    const float* fus_be = (const float*)d_in[13];
    float* out = (float*)d_out;

    k_sig<<<NPTS/256, 256>>>(x, path);
    k_raw<<<BB*JJ, 256>>>(x, raw_w, raw_b);
    k_gemm_ps<<<NPTS/128, 256>>>(ps_w, ps_b);
    dim3 rg(RCHUNKS, CO);
    k_reduce<<<rg, 256>>>(0);
    k_reduce<<<rg, 256>>>(1);
    k_fin1<<<1, 256>>>(raw_g, raw_be, ps_g, ps_be);
    k_gemm_fus<<<NPTS/128, 256>>>(fus_w, fus_b);
    k_reduce<<<rg, 256>>>(2);
    k_fin2<<<1, 128>>>(fus_g, fus_be);
    k_out<<<(CO*NPTS)/256, 256>>>(out);
}

// round 3
// speedup vs baseline: 1.9450x; 1.9450x over previous
#include <cuda_runtime.h>
#include <cuda_bf16.h>
#include <stdint.h>

#define BB 64
#define CC 3
#define JJ 11
#define TT 512
#define CO 128
#define NPTS (BB*JJ*TT)      /* 360448 = 2816*128 = 44*8192 */
#define SIGC 84
#define K1A 168              /* ps actual K */
#define K2A 256              /* fus actual K */
#define NT 128               /* points per GEMM CTA tile */
#define GRIDG (NPTS/NT)      /* 2816 gemm tiles */
#define UCHUNKS 44           /* NPTS/44 = 8192 */

// ---------------- static scratch ----------------
__device__ float g_S[K1A * NPTS];            // sig, channel-major [k][p]
__device__ float g_UV[(size_t)K2A * NPTS];   // rows 0..127 = U, 128..255 = V
__device__ float g_F[(size_t)CO * NPTS];     // fus pre-BN, channel-major
__device__ __nv_bfloat16 g_Aps_hi[3*8192],  g_Aps_lo[3*8192];   // [kc][o][kk]
__device__ __nv_bfloat16 g_Afus_hi[4*8192], g_Afus_lo[4*8192];
__device__ float g_pU[UCHUNKS*CO],  g_pUQ[UCHUNKS*CO];
__device__ float g_pV[GRIDG*CO],    g_pVQ[GRIDG*CO];
__device__ float g_pF[GRIDG*CO],    g_pFQ[GRIDG*CO];
__device__ float g_sc1[K2A], g_bi1[K2A];
__device__ float g_sc2[CO],  g_bi2[CO];

// ---------------- mma/ldmatrix helpers (sm_80-level PTX) ----------------
__device__ __forceinline__ uint32_t smem_u32(const void* p) {
    uint32_t a;
    asm("{ .reg .u64 t; cvta.to.shared.u64 t, %1; cvt.u32.u64 %0, t; }" : "=r"(a) : "l"(p));
    return a;
}
__device__ __forceinline__ void ldsm_x4(uint32_t (&r)[4], uint32_t addr) {
    asm volatile("ldmatrix.sync.aligned.m8n8.x4.shared.b16 {%0,%1,%2,%3}, [%4];"
        : "=r"(r[0]), "=r"(r[1]), "=r"(r[2]), "=r"(r[3]) : "r"(addr));
}
__device__ __forceinline__ void ldsm_x2_t(uint32_t (&r)[2], uint32_t addr) {
    asm volatile("ldmatrix.sync.aligned.m8n8.x2.trans.shared.b16 {%0,%1}, [%2];"
        : "=r"(r[0]), "=r"(r[1]) : "r"(addr));
}
__device__ __forceinline__ void mma_bf16(float (&d)[4], const uint32_t (&a)[4],
                                         const uint32_t (&b)[2]) {
    asm volatile("mma.sync.aligned.m16n8k16.row.col.f32.bf16.bf16.f32 "
        "{%0,%1,%2,%3}, {%4,%5,%6,%7}, {%8,%9}, {%0,%1,%2,%3};"
        : "+f"(d[0]), "+f"(d[1]), "+f"(d[2]), "+f"(d[3])
        : "r"(a[0]), "r"(a[1]), "r"(a[2]), "r"(a[3]), "r"(b[0]), "r"(b[1]));
}
__device__ __forceinline__ uint32_t pack_hi(float a, float b, uint32_t& lo) {
    __nv_bfloat16 ha = __float2bfloat16(a), hb = __float2bfloat16(b);
    __nv_bfloat16 la = __float2bfloat16(a - __bfloat162float(ha));
    __nv_bfloat16 lb = __float2bfloat16(b - __bfloat162float(hb));
    lo = (uint32_t)__bfloat16_as_ushort(la) | ((uint32_t)__bfloat16_as_ushort(lb) << 16);
    return (uint32_t)__bfloat16_as_ushort(ha) | ((uint32_t)__bfloat16_as_ushort(hb) << 16);
}

// SMEM layout (bytes): A rows stride 72 el (144B), B rows stride 136 el (272B)
#define AS_H 0
#define AS_L 18432
#define BS_H 36864
#define BS_L 54272
#define SM_SC 71680
#define SM_BI 72704
#define SMEM_GEMM 73728

// ---------------- depth-3 signature Chen step (c = 4) ----------------
__device__ __forceinline__ void sig_step(float S1[4], float S2[16], float S3[64],
                                         const float d[4]) {
    float dd[16];
#pragma unroll
    for (int i = 0; i < 4; i++)
#pragma unroll
        for (int j = 0; j < 4; j++) dd[i*4+j] = d[i]*d[j];
    float a[4];
#pragma unroll
    for (int i = 0; i < 4; i++) a[i] = 0.5f*S1[i] + d[i]*(1.0f/6.0f);
#pragma unroll
    for (int i = 0; i < 4; i++)
#pragma unroll
        for (int j = 0; j < 4; j++)
#pragma unroll
            for (int k = 0; k < 4; k++)
                S3[i*16+j*4+k] += S2[i*4+j]*d[k] + a[i]*dd[j*4+k];
#pragma unroll
    for (int i = 0; i < 4; i++)
#pragma unroll
        for (int j = 0; j < 4; j++)
            S2[i*4+j] += S1[i]*d[j] + 0.5f*dd[i*4+j];
#pragma unroll
    for (int i = 0; i < 4; i++) S1[i] += d[i];
}

__device__ __forceinline__ void sig_write(int rowbase, int p,
                                          const float S1[4], const float S2[16],
                                          const float S3[64]) {
#pragma unroll
    for (int i = 0; i < 4; i++)  g_S[(rowbase + i)      * NPTS + p] = S1[i];
#pragma unroll
    for (int i = 0; i < 16; i++) g_S[(rowbase + 4 + i)  * NPTS + p] = S2[i];
#pragma unroll
    for (int i = 0; i < 64; i++) g_S[(rowbase + 20 + i) * NPTS + p] = S3[i];
}

// ---------------- K1: signatures ----------------
__global__ void k_sig(const float* __restrict__ x, const int* __restrict__ path) {
    int p = blockIdx.x * blockDim.x + threadIdx.x;
    if (p >= NPTS) return;
    int t  = p & (TT - 1);
    int bj = p >> 9;
    int j  = bj % JJ;
    int b  = bj / JJ;
    const float* xb = x + (size_t)b * CC * JJ * TT;

    float S1[4], S2[16], S3[64];
    float prev[3], cur[3], d[4];

#pragma unroll
    for (int i = 0; i < 4; i++)  S1[i] = 0.f;
#pragma unroll
    for (int i = 0; i < 16; i++) S2[i] = 0.f;
#pragma unroll
    for (int i = 0; i < 64; i++) S3[i] = 0.f;

    int j0 = path[j*3+0], j1 = path[j*3+1], j2 = path[j*3+2];
#pragma unroll
    for (int c = 0; c < 3; c++) prev[c] = xb[(c*JJ + j0)*TT + t];
    d[0] = 0.f; d[1] = prev[0]; d[2] = prev[1]; d[3] = prev[2];
    sig_step(S1, S2, S3, d);
#pragma unroll
    for (int c = 0; c < 3; c++) cur[c] = xb[(c*JJ + j1)*TT + t];
    d[0] = 0.5f;
#pragma unroll
    for (int c = 0; c < 3; c++) { d[c+1] = cur[c] - prev[c]; prev[c] = cur[c]; }
    sig_step(S1, S2, S3, d);
#pragma unroll
    for (int c = 0; c < 3; c++) cur[c] = xb[(c*JJ + j2)*TT + t];
    d[0] = 0.5f;
#pragma unroll
    for (int c = 0; c < 3; c++) d[c+1] = cur[c] - prev[c];
    sig_step(S1, S2, S3, d);
    sig_write(0, p, S1, S2, S3);

#pragma unroll
    for (int i = 0; i < 4; i++)  S1[i] = 0.f;
#pragma unroll
    for (int i = 0; i < 16; i++) S2[i] = 0.f;
#pragma unroll
    for (int i = 0; i < 64; i++) S3[i] = 0.f;

#pragma unroll
    for (int l = 0; l < 7; l++) {
        int tc = t + l - 3;
        tc = tc < 0 ? 0 : (tc > TT-1 ? TT-1 : tc);
#pragma unroll
        for (int c = 0; c < 3; c++) cur[c] = xb[(c*JJ + j)*TT + tc];
        if (l == 0) {
            d[0] = 0.f;
#pragma unroll
            for (int c = 0; c < 3; c++) d[c+1] = cur[c];
        } else {
            d[0] = 1.0f/6.0f;
#pragma unroll
            for (int c = 0; c < 3; c++) d[c+1] = cur[c] - prev[c];
        }
#pragma unroll
        for (int c = 0; c < 3; c++) prev[c] = cur[c];
        sig_step(S1, S2, S3, d);
    }
    sig_write(SIGC, p, S1, S2, S3);
}

// ---------------- K2: raw (1x3) conv + bias -> g_UV rows 0..127 ----------------
__global__ void k_raw(const float* __restrict__ x, const float* __restrict__ w,
                      const float* __restrict__ b) {
    __shared__ float xs[3][TT + 2];
    __shared__ float ws[CO * 9];
    __shared__ float bs[CO];
    int bj = blockIdx.x;
    int j = bj % JJ, bb = bj / JJ;
    int tid = threadIdx.x;

    for (int i = tid; i < 3*(TT+2); i += 256) {
        int c = i / (TT+2), tt = i % (TT+2);
        xs[c][tt] = (tt >= 1 && tt <= TT) ? x[((bb*3 + c)*JJ + j)*TT + tt - 1] : 0.f;
    }
    for (int i = tid; i < CO*9; i += 256) ws[i] = w[i];
    if (tid < CO) bs[tid] = b[tid];
    __syncthreads();

    int t0 = tid, t1 = 256 + tid;
    float xv0[3][3], xv1[3][3];
#pragma unroll
    for (int c = 0; c < 3; c++)
#pragma unroll
        for (int kw = 0; kw < 3; kw++) {
            xv0[c][kw] = xs[c][t0 + kw];
            xv1[c][kw] = xs[c][t1 + kw];
        }
    int pbase = bj * TT;
    for (int o = 0; o < CO; o++) {
        float a0 = bs[o], a1 = bs[o];
#pragma unroll
        for (int c = 0; c < 3; c++)
#pragma unroll
            for (int kw = 0; kw < 3; kw++) {
                float wv = ws[o*9 + c*3 + kw];
                a0 = fmaf(xv0[c][kw], wv, a0);
                a1 = fmaf(xv1[c][kw], wv, a1);
            }
        g_UV[(size_t)o*NPTS + pbase + t0] = a0;
        g_UV[(size_t)o*NPTS + pbase + t1] = a1;
    }
}

// ---------------- prep: bf16 hi/lo weight images, [kc][o][kk] ----------------
__global__ void k_prep(const float* __restrict__ psw, const float* __restrict__ fusw) {
    int which = blockIdx.x;
    const float* W = which ? fusw : psw;
    int K  = which ? 256 : 168;
    int KP = which ? 256 : 192;
    __nv_bfloat16* AH = which ? g_Afus_hi : g_Aps_hi;
    __nv_bfloat16* AL = which ? g_Afus_lo : g_Aps_lo;
    for (int idx = threadIdx.x; idx < 128*KP; idx += blockDim.x) {
        int o = idx / KP, k = idx % KP;
        float v = (k < K) ? W[o*K + k] : 0.f;
        __nv_bfloat16 h = __float2bfloat16(v);
        __nv_bfloat16 l = __float2bfloat16(v - __bfloat162float(h));
        int kc = k >> 6, kk = k & 63;
        AH[kc*8192 + o*64 + kk] = h;
        AL[kc*8192 + o*64 + kk] = l;
    }
}

// ---------------- tensor-core GEMM via mma.sync: D[128ch][128pts]/CTA ----------------
__global__ void __launch_bounds__(256, 2) k_gemm_tc(int mode, const float* __restrict__ bias) {
    extern __shared__ char smc[];
    __shared__ float sS[CO], sQ[CO];
    __nv_bfloat16* As_h = (__nv_bfloat16*)(smc + AS_H);
    __nv_bfloat16* As_l = (__nv_bfloat16*)(smc + AS_L);
    __nv_bfloat16* Bs_h = (__nv_bfloat16*)(smc + BS_H);
    __nv_bfloat16* Bs_l = (__nv_bfloat16*)(smc + BS_L);
    float* s_sc = (float*)(smc + SM_SC);
    float* s_bi = (float*)(smc + SM_BI);
    uint32_t sb = smem_u32(smc);

    int tid = threadIdx.x;
    int warp = tid >> 5, lane = tid & 31;
    int wm = (warp >> 2) * 64;
    int wn = (warp & 3) * 32;

    const float* Bsrc; int kact, kchunks;
    const __nv_bfloat16 *Ahg, *Alg;
    float *Out, *pS, *pQ; int affine;
    if (mode == 0) {
        Bsrc = g_S; kact = K1A; kchunks = 3;
        Ahg = g_Aps_hi; Alg = g_Aps_lo;
        Out = g_UV + (size_t)CO*NPTS; pS = g_pV; pQ = g_pVQ; affine = 0;
    } else {
        Bsrc = g_UV; kact = K2A; kchunks = 4;
        Ahg = g_Afus_hi; Alg = g_Afus_lo;
        Out = g_F; pS = g_pF; pQ = g_pFQ; affine = 1;
    }

    if (affine)
        for (int i = tid; i < K2A; i += 256) { s_sc[i] = g_sc1[i]; s_bi[i] = g_bi1[i]; }
    if (tid < CO) { sS[tid] = 0.f; sQ[tid] = 0.f; }

    float acc[4][4][4];
#pragma unroll
    for (int i = 0; i < 4; i++)
#pragma unroll
        for (int j = 0; j < 4; j++)
#pragma unroll
            for (int r = 0; r < 4; r++) acc[i][j][r] = 0.f;

    int p0 = blockIdx.x * NT;
    __syncthreads();

    for (int kc = 0; kc < kchunks; kc++) {
        // ---- A chunk -> SMEM (stride 72 el) ----
        for (int i = tid; i < 2048; i += 256) {       // 2048 uint2 of 4 bf16
            int o = i >> 4, k4 = (i & 15) << 2;
            uint2 vh = ((const uint2*)(Ahg + kc*8192))[i];
            uint2 vl = ((const uint2*)(Alg + kc*8192))[i];
            *(uint2*)(As_h + o*72 + k4) = vh;
            *(uint2*)(As_l + o*72 + k4) = vl;
        }
        // ---- B chunk: [64k][128p], fp32 -> bf16 hi/lo (stride 136 el) ----
#pragma unroll
        for (int it = 0; it < 8; it++) {
            int kl = it*8 + warp;
            int kg = kc*64 + kl;
            int p  = lane << 2;
            float4 v = make_float4(0.f, 0.f, 0.f, 0.f);
            if (kg < kact) {
                v = *(const float4*)&Bsrc[(size_t)kg*NPTS + p0 + p];
                if (affine) {
                    float sc = s_sc[kg], bi = s_bi[kg];
                    v.x = fmaxf(fmaf(v.x, sc, bi), 0.f);
                    v.y = fmaxf(fmaf(v.y, sc, bi), 0.f);
                    v.z = fmaxf(fmaf(v.z, sc, bi), 0.f);
                    v.w = fmaxf(fmaf(v.w, sc, bi), 0.f);
                }
            }
            uint32_t l0, l1;
            uint32_t h0 = pack_hi(v.x, v.y, l0);
            uint32_t h1 = pack_hi(v.z, v.w, l1);
            *(uint2*)(Bs_h + kl*136 + p) = make_uint2(h0, h1);
            *(uint2*)(Bs_l + kl*136 + p) = make_uint2(l0, l1);
        }
        __syncthreads();
        // ---- compute 4 k16 steps ----
#pragma unroll
        for (int ks = 0; ks < 4; ks++) {
            int k0 = ks * 16;
            uint32_t ah[4][4], al[4][4];
#pragma unroll
            for (int i = 0; i < 4; i++) {
                uint32_t off = (uint32_t)((wm + i*16 + (lane & 15))*144
                                        + (k0 + (lane >> 4)*8)*2);
                ldsm_x4(ah[i], sb + AS_H + off);
                ldsm_x4(al[i], sb + AS_L + off);
            }
#pragma unroll
            for (int j = 0; j < 4; j++) {
                uint32_t bh[2], bl[2];
                uint32_t boff = (uint32_t)((k0 + (lane & 15))*272 + (wn + j*8)*2);
                ldsm_x2_t(bh, sb + BS_H + boff);
                ldsm_x2_t(bl, sb + BS_L + boff);
#pragma unroll
                for (int i = 0; i < 4; i++) {
                    mma_bf16(acc[i][j], ah[i], bh);
                    mma_bf16(acc[i][j], ah[i], bl);
                    mma_bf16(acc[i][j], al[i], bh);
                }
            }
        }
        __syncthreads();
    }

    // ---- epilogue: bias, store channel-major, fused BN partials ----
#pragma unroll
    for (int i = 0; i < 4; i++) {
        int c0 = wm + i*16 + (lane >> 2);
        int c1 = c0 + 8;
        float b0 = bias[c0], b1 = bias[c1];
        float s0 = 0.f, q0 = 0.f, s1 = 0.f, q1 = 0.f;
#pragma unroll
        for (int j = 0; j < 4; j++) {
            float v00 = acc[i][j][0] + b0, v01 = acc[i][j][1] + b0;
            float v10 = acc[i][j][2] + b1, v11 = acc[i][j][3] + b1;
            int p = p0 + wn + j*8 + ((lane & 3) << 1);
            *(float2*)&Out[(size_t)c0*NPTS + p] = make_float2(v00, v01);
            *(float2*)&Out[(size_t)c1*NPTS + p] = make_float2(v10, v11);
            s0 += v00 + v01; q0 += v00*v00 + v01*v01;
            s1 += v10 + v11; q1 += v10*v10 + v11*v11;
        }
#pragma unroll
        for (int d = 1; d < 4; d <<= 1) {
            s0 += __shfl_xor_sync(0xffffffffu, s0, d);
            q0 += __shfl_xor_sync(0xffffffffu, q0, d);
            s1 += __shfl_xor_sync(0xffffffffu, s1, d);
            q1 += __shfl_xor_sync(0xffffffffu, q1, d);
        }
        if ((lane & 3) == 0) {
            atomicAdd(&sS[c0], s0); atomicAdd(&sQ[c0], q0);
            atomicAdd(&sS[c1], s1); atomicAdd(&sQ[c1], q1);
        }
    }
    __syncthreads();
    if (tid < CO) {
        pS[blockIdx.x*CO + tid] = sS[tid];
        pQ[blockIdx.x*CO + tid] = sQ[tid];
    }
}

// ---------------- U reduction (channel-major, float4) ----------------
__global__ void k_redU() {
    int chunk = blockIdx.x, c = blockIdx.y;
    const float4* row = (const float4*)(g_UV + (size_t)c*NPTS + chunk*8192);
    float s = 0.f, q = 0.f;
    for (int i = threadIdx.x; i < 2048; i += 256) {
        float4 v = row[i];
        s += v.x + v.y + v.z + v.w;
        q += v.x*v.x + v.y*v.y + v.z*v.z + v.w*v.w;
    }
    __shared__ float sh[512];
    sh[threadIdx.x] = s; sh[256 + threadIdx.x] = q;
    __syncthreads();
    for (int st = 128; st; st >>= 1) {
        if (threadIdx.x < st) {
            sh[threadIdx.x]       += sh[threadIdx.x + st];
            sh[256 + threadIdx.x] += sh[256 + threadIdx.x + st];
        }
        __syncthreads();
    }
    if (threadIdx.x == 0) {
        g_pU[chunk*CO + c]  = sh[0];
        g_pUQ[chunk*CO + c] = sh[256];
    }
}

// ---------------- finalize BN affines ----------------
__global__ void k_fin1(const float* __restrict__ rg, const float* __restrict__ rb,
                       const float* __restrict__ pg, const float* __restrict__ pb) {
    int c = blockIdx.x;   // 0..255
    float s = 0.f, q = 0.f;
    if (c < CO) {
        for (int i = threadIdx.x; i < UCHUNKS; i += 128) { s += g_pU[i*CO + c]; q += g_pUQ[i*CO + c]; }
    } else {
        int cc = c - CO;
        for (int i = threadIdx.x; i < GRIDG; i += 128) { s += g_pV[i*CO + cc]; q += g_pVQ[i*CO + cc]; }
    }
    __shared__ float sh[256];
    sh[threadIdx.x] = s; sh[128 + threadIdx.x] = q;
    __syncthreads();
    for (int st = 64; st; st >>= 1) {
        if (threadIdx.x < st) {
            sh[threadIdx.x]       += sh[threadIdx.x + st];
            sh[128 + threadIdx.x] += sh[128 + threadIdx.x + st];
        }
        __syncthreads();
    }
    if (threadIdx.x == 0) {
        float mean = sh[0] / (float)NPTS;
        float var  = sh[128] / (float)NPTS - mean*mean;
        float rstd = rsqrtf(var + 1e-5f);
        float g  = (c < CO) ? rg[c] : pg[c - CO];
        float be = (c < CO) ? rb[c] : pb[c - CO];
        g_sc1[c] = rstd * g;
        g_bi1[c] = be - mean * rstd * g;
    }
}

__global__ void k_fin2(const float* __restrict__ fg, const float* __restrict__ fb) {
    int c = blockIdx.x;   // 0..127
    float s = 0.f, q = 0.f;
    for (int i = threadIdx.x; i < GRIDG; i += 128) { s += g_pF[i*CO + c]; q += g_pFQ[i*CO + c]; }
    __shared__ float sh[256];
    sh[threadIdx.x] = s; sh[128 + threadIdx.x] = q;
    __syncthreads();
    for (int st = 64; st; st >>= 1) {
        if (threadIdx.x < st) {
            sh[threadIdx.x]       += sh[threadIdx.x + st];
            sh[128 + threadIdx.x] += sh[128 + threadIdx.x + st];
        }
        __syncthreads();
    }
    if (threadIdx.x == 0) {
        float mean = sh[0] / (float)NPTS;
        float var  = sh[128] / (float)NPTS - mean*mean;
        float rstd = rsqrtf(var + 1e-5f);
        g_sc2[c] = rstd * fg[c];
        g_bi2[c] = fb[c] - mean * rstd * fg[c];
    }
}

// ---------------- final affine + relu + reshape ----------------
__global__ void k_out(float* __restrict__ out) {
    int e = blockIdx.x * 256 + threadIdx.x;
    int o = e / NPTS;
    int p = e - o * NPTS;
    int t  = p & (TT - 1);
    int bj = p >> 9;
    int j  = bj % JJ;
    int b  = bj / JJ;
    float v = fmaf(g_F[e], g_sc2[o], g_bi2[o]);
    out[((b*CO + o)*JJ + j)*TT + t] = fmaxf(v, 0.f);
}

// ---------------- launcher ----------------
extern "C" void kernel_launch(void* const* d_in, const int* in_sizes, int n_in,
                              void* d_out, int out_size) {
    const float* x      = (const float*)d_in[0];
    const int*   path   = (const int*)  d_in[1];
    const float* raw_w  = (const float*)d_in[2];
    const float* raw_b  = (const float*)d_in[3];
    const float* raw_g  = (const float*)d_in[4];
    const float* raw_be = (const float*)d_in[5];
    const float* ps_w   = (const float*)d_in[6];
    const float* ps_b   = (const float*)d_in[7];
    const float* ps_g   = (const float*)d_in[8];
    const float* ps_be  = (const float*)d_in[9];
    const float* fus_w  = (const float*)d_in[10];
    const float* fus_b  = (const float*)d_in[11];
    const float* fus_g  = (const float*)d_in[12];
    const float* fus_be = (const float*)d_in[13];
    float* out = (float*)d_out;

    cudaFuncSetAttribute(k_gemm_tc, cudaFuncAttributeMaxDynamicSharedMemorySize, SMEM_GEMM);

    k_prep<<<2, 256>>>(ps_w, fus_w);
    k_sig<<<NPTS/256, 256>>>(x, path);
    k_raw<<<BB*JJ, 256>>>(x, raw_w, raw_b);
    k_redU<<<dim3(UCHUNKS, CO), 256>>>();
    k_gemm_tc<<<GRIDG, 256, SMEM_GEMM>>>(0, ps_b);
    k_fin1<<<2*CO, 128>>>(raw_g, raw_be, ps_g, ps_be);
    k_gemm_tc<<<GRIDG, 256, SMEM_GEMM>>>(1, fus_b);
    k_fin2<<<CO, 128>>>(fus_g, fus_be);
    k_out<<<(CO*NPTS)/256, 256>>>(out);
}

// round 4
// speedup vs baseline: 2.0416x; 1.0497x over previous
#include <cuda_runtime.h>
#include <cuda_bf16.h>
#include <stdint.h>

#define BB 64
#define CC 3
#define JJ 11
#define TT 512
#define CO 128
#define NPTS (BB*JJ*TT)      /* 360448 = 2816*128 */
#define SIGC 84
#define K1A 168              /* ps actual K */
#define K2A 256              /* fus actual K */
#define NT 128               /* points per GEMM CTA tile */
#define GRIDG (NPTS/NT)      /* 2816 gemm tiles */
#define RAWG (BB*JJ)         /* 704 raw-conv CTAs */

// ---------------- static scratch ----------------
__device__ uint32_t g_Spk[K1A * NPTS];       // sig packed (bf16 hi | bf16 lo<<16), [k][p]
__device__ float g_UV[(size_t)K2A * NPTS];   // rows 0..127 = U, 128..255 = V
__device__ float g_F[(size_t)CO * NPTS];     // fus pre-BN, channel-major
__device__ __nv_bfloat16 g_Aps_hi[3*8192],  g_Aps_lo[3*8192];   // [kc][o][kk]
__device__ __nv_bfloat16 g_Afus_hi[4*8192], g_Afus_lo[4*8192];
__device__ float g_pU[RAWG*CO],   g_pUQ[RAWG*CO];
__device__ float g_pV[GRIDG*CO],  g_pVQ[GRIDG*CO];
__device__ float g_pF[GRIDG*CO],  g_pFQ[GRIDG*CO];
__device__ float g_sc1[K2A], g_bi1[K2A];
__device__ float g_sc2[CO],  g_bi2[CO];

// ---------------- mma/ldmatrix helpers (sm_80-level PTX) ----------------
__device__ __forceinline__ uint32_t smem_u32(const void* p) {
    uint32_t a;
    asm("{ .reg .u64 t; cvta.to.shared.u64 t, %1; cvt.u32.u64 %0, t; }" : "=r"(a) : "l"(p));
    return a;
}
__device__ __forceinline__ void ldsm_x4(uint32_t (&r)[4], uint32_t addr) {
    asm volatile("ldmatrix.sync.aligned.m8n8.x4.shared.b16 {%0,%1,%2,%3}, [%4];"
        : "=r"(r[0]), "=r"(r[1]), "=r"(r[2]), "=r"(r[3]) : "r"(addr));
}
__device__ __forceinline__ void ldsm_x2_t(uint32_t (&r)[2], uint32_t addr) {
    asm volatile("ldmatrix.sync.aligned.m8n8.x2.trans.shared.b16 {%0,%1}, [%2];"
        : "=r"(r[0]), "=r"(r[1]) : "r"(addr));
}
__device__ __forceinline__ void mma_bf16(float (&d)[4], const uint32_t (&a)[4],
                                         const uint32_t (&b)[2]) {
    asm volatile("mma.sync.aligned.m16n8k16.row.col.f32.bf16.bf16.f32 "
        "{%0,%1,%2,%3}, {%4,%5,%6,%7}, {%8,%9}, {%0,%1,%2,%3};"
        : "+f"(d[0]), "+f"(d[1]), "+f"(d[2]), "+f"(d[3])
        : "r"(a[0]), "r"(a[1]), "r"(a[2]), "r"(a[3]), "r"(b[0]), "r"(b[1]));
}
__device__ __forceinline__ uint32_t pack_hi(float a, float b, uint32_t& lo) {
    __nv_bfloat16 ha = __float2bfloat16(a), hb = __float2bfloat16(b);
    __nv_bfloat16 la = __float2bfloat16(a - __bfloat162float(ha));
    __nv_bfloat16 lb = __float2bfloat16(b - __bfloat162float(hb));
    lo = (uint32_t)__bfloat16_as_ushort(la) | ((uint32_t)__bfloat16_as_ushort(lb) << 16);
    return (uint32_t)__bfloat16_as_ushort(ha) | ((uint32_t)__bfloat16_as_ushort(hb) << 16);
}
__device__ __forceinline__ uint32_t pack1(float v) {
    __nv_bfloat16 h = __float2bfloat16(v);
    __nv_bfloat16 l = __float2bfloat16(v - __bfloat162float(h));
    return (uint32_t)__bfloat16_as_ushort(h) | ((uint32_t)__bfloat16_as_ushort(l) << 16);
}

// SMEM layout (bytes): A rows stride 72 el (144B), B rows stride 136 el (272B)
#define AS_H 0
#define AS_L 18432
#define BS_H 36864
#define BS_L 54272
#define SM_SC 71680
#define SM_BI 72704
#define SMEM_GEMM 73728

// ---------------- depth-3 signature Chen step (c = 4) ----------------
__device__ __forceinline__ void sig_step(float S1[4], float S2[16], float S3[64],
                                         const float d[4]) {
    float dd[16];
#pragma unroll
    for (int i = 0; i < 4; i++)
#pragma unroll
        for (int j = 0; j < 4; j++) dd[i*4+j] = d[i]*d[j];
    float a[4];
#pragma unroll
    for (int i = 0; i < 4; i++) a[i] = 0.5f*S1[i] + d[i]*(1.0f/6.0f);
#pragma unroll
    for (int i = 0; i < 4; i++)
#pragma unroll
        for (int j = 0; j < 4; j++)
#pragma unroll
            for (int k = 0; k < 4; k++)
                S3[i*16+j*4+k] += S2[i*4+j]*d[k] + a[i]*dd[j*4+k];
#pragma unroll
    for (int i = 0; i < 4; i++)
#pragma unroll
        for (int j = 0; j < 4; j++)
            S2[i*4+j] += S1[i]*d[j] + 0.5f*dd[i*4+j];
#pragma unroll
    for (int i = 0; i < 4; i++) S1[i] += d[i];
}

__device__ __forceinline__ void sig_write(int rowbase, int p,
                                          const float S1[4], const float S2[16],
                                          const float S3[64]) {
#pragma unroll
    for (int i = 0; i < 4; i++)  g_Spk[(rowbase + i)      * NPTS + p] = pack1(S1[i]);
#pragma unroll
    for (int i = 0; i < 16; i++) g_Spk[(rowbase + 4 + i)  * NPTS + p] = pack1(S2[i]);
#pragma unroll
    for (int i = 0; i < 64; i++) g_Spk[(rowbase + 20 + i) * NPTS + p] = pack1(S3[i]);
}

// ---------------- K1: signatures ----------------
__global__ void k_sig(const float* __restrict__ x, const int* __restrict__ path) {
    int p = blockIdx.x * blockDim.x + threadIdx.x;
    if (p >= NPTS) return;
    int t  = p & (TT - 1);
    int bj = p >> 9;
    int j  = bj % JJ;
    int b  = bj / JJ;
    const float* xb = x + (size_t)b * CC * JJ * TT;

    float S1[4], S2[16], S3[64];
    float prev[3], cur[3], d[4];

#pragma unroll
    for (int i = 0; i < 4; i++)  S1[i] = 0.f;
#pragma unroll
    for (int i = 0; i < 16; i++) S2[i] = 0.f;
#pragma unroll
    for (int i = 0; i < 64; i++) S3[i] = 0.f;

    int j0 = path[j*3+0], j1 = path[j*3+1], j2 = path[j*3+2];
#pragma unroll
    for (int c = 0; c < 3; c++) prev[c] = xb[(c*JJ + j0)*TT + t];
    d[0] = 0.f; d[1] = prev[0]; d[2] = prev[1]; d[3] = prev[2];
    sig_step(S1, S2, S3, d);
#pragma unroll
    for (int c = 0; c < 3; c++) cur[c] = xb[(c*JJ + j1)*TT + t];
    d[0] = 0.5f;
#pragma unroll
    for (int c = 0; c < 3; c++) { d[c+1] = cur[c] - prev[c]; prev[c] = cur[c]; }
    sig_step(S1, S2, S3, d);
#pragma unroll
    for (int c = 0; c < 3; c++) cur[c] = xb[(c*JJ + j2)*TT + t];
    d[0] = 0.5f;
#pragma unroll
    for (int c = 0; c < 3; c++) d[c+1] = cur[c] - prev[c];
    sig_step(S1, S2, S3, d);
    sig_write(0, p, S1, S2, S3);

#pragma unroll
    for (int i = 0; i < 4; i++)  S1[i] = 0.f;
#pragma unroll
    for (int i = 0; i < 16; i++) S2[i] = 0.f;
#pragma unroll
    for (int i = 0; i < 64; i++) S3[i] = 0.f;

#pragma unroll
    for (int l = 0; l < 7; l++) {
        int tc = t + l - 3;
        tc = tc < 0 ? 0 : (tc > TT-1 ? TT-1 : tc);
#pragma unroll
        for (int c = 0; c < 3; c++) cur[c] = xb[(c*JJ + j)*TT + tc];
        if (l == 0) {
            d[0] = 0.f;
#pragma unroll
            for (int c = 0; c < 3; c++) d[c+1] = cur[c];
        } else {
            d[0] = 1.0f/6.0f;
#pragma unroll
            for (int c = 0; c < 3; c++) d[c+1] = cur[c] - prev[c];
        }
#pragma unroll
        for (int c = 0; c < 3; c++) prev[c] = cur[c];
        sig_step(S1, S2, S3, d);
    }
    sig_write(SIGC, p, S1, S2, S3);
}

// ---------------- K2: raw conv + bias + fused BN partials ----------------
__global__ void k_raw(const float* __restrict__ x, const float* __restrict__ w,
                      const float* __restrict__ b) {
    __shared__ float xs[3][TT + 2];
    __shared__ float ws[CO * 9];
    __shared__ float bs[CO];
    int bj = blockIdx.x;
    int j = bj % JJ, bb = bj / JJ;
    int tid = threadIdx.x;
    int warp = tid >> 5, lane = tid & 31;

    for (int i = tid; i < 3*(TT+2); i += 256) {
        int c = i / (TT+2), tt = i % (TT+2);
        xs[c][tt] = (tt >= 1 && tt <= TT) ? x[((bb*3 + c)*JJ + j)*TT + tt - 1] : 0.f;
    }
    for (int i = tid; i < CO*9; i += 256) ws[i] = w[i];
    if (tid < CO) bs[tid] = b[tid];
    __syncthreads();

    int pbase = bj * TT;
    // warp owns channels [warp*16, warp*16+16)
#pragma unroll 1
    for (int oi = 0; oi < 16; oi++) {
        int o = warp*16 + oi;
        float wr[9];
#pragma unroll
        for (int i = 0; i < 9; i++) wr[i] = ws[o*9 + i];
        float bo = bs[o];
        float s = 0.f, q = 0.f;
        float* orow = g_UV + (size_t)o*NPTS + pbase;
#pragma unroll
        for (int i = 0; i < 16; i++) {
            int t = i*32 + lane;
            float a = bo;
#pragma unroll
            for (int c = 0; c < 3; c++)
#pragma unroll
                for (int kw = 0; kw < 3; kw++)
                    a = fmaf(xs[c][t + kw], wr[c*3 + kw], a);
            orow[t] = a;
            s += a; q += a*a;
        }
#pragma unroll
        for (int d = 16; d; d >>= 1) {
            s += __shfl_xor_sync(0xffffffffu, s, d);
            q += __shfl_xor_sync(0xffffffffu, q, d);
        }
        if (lane == 0) { g_pU[bj*CO + o] = s; g_pUQ[bj*CO + o] = q; }
    }
}

// ---------------- prep: bf16 hi/lo weight images, [kc][o][kk] ----------------
__global__ void k_prep(const float* __restrict__ psw, const float* __restrict__ fusw) {
    int which = blockIdx.x;
    const float* W = which ? fusw : psw;
    int K  = which ? 256 : 168;
    int KP = which ? 256 : 192;
    __nv_bfloat16* AH = which ? g_Afus_hi : g_Aps_hi;
    __nv_bfloat16* AL = which ? g_Afus_lo : g_Aps_lo;
    for (int idx = threadIdx.x; idx < 128*KP; idx += blockDim.x) {
        int o = idx / KP, k = idx % KP;
        float v = (k < K) ? W[o*K + k] : 0.f;
        __nv_bfloat16 h = __float2bfloat16(v);
        __nv_bfloat16 l = __float2bfloat16(v - __bfloat162float(h));
        int kc = k >> 6, kk = k & 63;
        AH[kc*8192 + o*64 + kk] = h;
        AL[kc*8192 + o*64 + kk] = l;
    }
}

// ---------------- tensor-core GEMM via mma.sync: D[128ch][128pts]/CTA ----------------
__global__ void __launch_bounds__(256, 2) k_gemm_tc(int mode, const float* __restrict__ bias) {
    extern __shared__ char smc[];
    __shared__ float sS[CO], sQ[CO];
    __nv_bfloat16* As_h = (__nv_bfloat16*)(smc + AS_H);
    __nv_bfloat16* As_l = (__nv_bfloat16*)(smc + AS_L);
    __nv_bfloat16* Bs_h = (__nv_bfloat16*)(smc + BS_H);
    __nv_bfloat16* Bs_l = (__nv_bfloat16*)(smc + BS_L);
    float* s_sc = (float*)(smc + SM_SC);
    float* s_bi = (float*)(smc + SM_BI);
    uint32_t sb = smem_u32(smc);

    int tid = threadIdx.x;
    int warp = tid >> 5, lane = tid & 31;
    int wm = (warp >> 2) * 64;
    int wn = (warp & 3) * 32;

    int kact, kchunks;
    const __nv_bfloat16 *Ahg, *Alg;
    float *Out, *pS, *pQ; int affine;
    if (mode == 0) {
        kact = K1A; kchunks = 3;
        Ahg = g_Aps_hi; Alg = g_Aps_lo;
        Out = g_UV + (size_t)CO*NPTS; pS = g_pV; pQ = g_pVQ; affine = 0;
    } else {
        kact = K2A; kchunks = 4;
        Ahg = g_Afus_hi; Alg = g_Afus_lo;
        Out = g_F; pS = g_pF; pQ = g_pFQ; affine = 1;
    }

    if (affine)
        for (int i = tid; i < K2A; i += 256) { s_sc[i] = g_sc1[i]; s_bi[i] = g_bi1[i]; }
    if (tid < CO) { sS[tid] = 0.f; sQ[tid] = 0.f; }

    float acc[4][4][4];
#pragma unroll
    for (int i = 0; i < 4; i++)
#pragma unroll
        for (int j = 0; j < 4; j++)
#pragma unroll
            for (int r = 0; r < 4; r++) acc[i][j][r] = 0.f;

    int p0 = blockIdx.x * NT;
    __syncthreads();

    for (int kc = 0; kc < kchunks; kc++) {
        // ---- A chunk -> SMEM (stride 72 el), uint4 copies ----
        for (int i = tid; i < 1024; i += 256) {      // 1024 uint4 of 8 bf16
            int o = i >> 3, k8 = (i & 7) << 3;
            uint4 vh = ((const uint4*)(Ahg + kc*8192))[i];
            uint4 vl = ((const uint4*)(Alg + kc*8192))[i];
            *(uint4*)(As_h + o*72 + k8) = vh;
            *(uint4*)(As_l + o*72 + k8) = vl;
        }
        // ---- B chunk: [64k][128p] ----
        if (affine) {
#pragma unroll
            for (int it = 0; it < 8; it++) {
                int kl = it*8 + warp;
                int kg = kc*64 + kl;
                int p  = lane << 2;
                float4 v = *(const float4*)&g_UV[(size_t)kg*NPTS + p0 + p];
                float sc = s_sc[kg], bi = s_bi[kg];
                v.x = fmaxf(fmaf(v.x, sc, bi), 0.f);
                v.y = fmaxf(fmaf(v.y, sc, bi), 0.f);
                v.z = fmaxf(fmaf(v.z, sc, bi), 0.f);
                v.w = fmaxf(fmaf(v.w, sc, bi), 0.f);
                uint32_t l0, l1;
                uint32_t h0 = pack_hi(v.x, v.y, l0);
                uint32_t h1 = pack_hi(v.z, v.w, l1);
                *(uint2*)(Bs_h + kl*136 + p) = make_uint2(h0, h1);
                *(uint2*)(Bs_l + kl*136 + p) = make_uint2(l0, l1);
            }
        } else {
#pragma unroll
            for (int it = 0; it < 8; it++) {
                int kl = it*8 + warp;
                int kg = kc*64 + kl;
                int p  = lane << 2;
                uint2 h = make_uint2(0u, 0u), l = make_uint2(0u, 0u);
                if (kg < K1A) {
                    uint4 v = *(const uint4*)&g_Spk[(size_t)kg*NPTS + p0 + p];
                    h.x = __byte_perm(v.x, v.y, 0x5410);
                    l.x = __byte_perm(v.x, v.y, 0x7632);
                    h.y = __byte_perm(v.z, v.w, 0x5410);
                    l.y = __byte_perm(v.z, v.w, 0x7632);
                }
                *(uint2*)(Bs_h + kl*136 + p) = h;
                *(uint2*)(Bs_l + kl*136 + p) = l;
            }
        }
        __syncthreads();
        // ---- compute 4 k16 steps ----
#pragma unroll
        for (int ks = 0; ks < 4; ks++) {
            int k0 = ks * 16;
            uint32_t ah[4][4], al[4][4];
#pragma unroll
            for (int i = 0; i < 4; i++) {
                uint32_t off = (uint32_t)((wm + i*16 + (lane & 15))*144
                                        + (k0 + (lane >> 4)*8)*2);
                ldsm_x4(ah[i], sb + AS_H + off);
                ldsm_x4(al[i], sb + AS_L + off);
            }
#pragma unroll
            for (int j = 0; j < 4; j++) {
                uint32_t bh[2], bl[2];
                uint32_t boff = (uint32_t)((k0 + (lane & 15))*272 + (wn + j*8)*2);
                ldsm_x2_t(bh, sb + BS_H + boff);
                ldsm_x2_t(bl, sb + BS_L + boff);
#pragma unroll
                for (int i = 0; i < 4; i++) {
                    mma_bf16(acc[i][j], ah[i], bh);
                    mma_bf16(acc[i][j], ah[i], bl);
                    mma_bf16(acc[i][j], al[i], bh);
                }
            }
        }
        __syncthreads();
    }

    // ---- epilogue: bias, store channel-major, fused BN partials ----
#pragma unroll
    for (int i = 0; i < 4; i++) {
        int c0 = wm + i*16 + (lane >> 2);
        int c1 = c0 + 8;
        float b0 = bias[c0], b1 = bias[c1];
        float s0 = 0.f, q0 = 0.f, s1 = 0.f, q1 = 0.f;
#pragma unroll
        for (int j = 0; j < 4; j++) {
            float v00 = acc[i][j][0] + b0, v01 = acc[i][j][1] + b0;
            float v10 = acc[i][j][2] + b1, v11 = acc[i][j][3] + b1;
            int p = p0 + wn + j*8 + ((lane & 3) << 1);
            *(float2*)&Out[(size_t)c0*NPTS + p] = make_float2(v00, v01);
            *(float2*)&Out[(size_t)c1*NPTS + p] = make_float2(v10, v11);
            s0 += v00 + v01; q0 += v00*v00 + v01*v01;
            s1 += v10 + v11; q1 += v10*v10 + v11*v11;
        }
#pragma unroll
        for (int d = 1; d < 4; d <<= 1) {
            s0 += __shfl_xor_sync(0xffffffffu, s0, d);
            q0 += __shfl_xor_sync(0xffffffffu, q0, d);
            s1 += __shfl_xor_sync(0xffffffffu, s1, d);
            q1 += __shfl_xor_sync(0xffffffffu, q1, d);
        }
        if ((lane & 3) == 0) {
            atomicAdd(&sS[c0], s0); atomicAdd(&sQ[c0], q0);
            atomicAdd(&sS[c1], s1); atomicAdd(&sQ[c1], q1);
        }
    }
    __syncthreads();
    if (tid < CO) {
        pS[blockIdx.x*CO + tid] = sS[tid];
        pQ[blockIdx.x*CO + tid] = sQ[tid];
    }
}

// ---------------- finalize BN affines ----------------
__global__ void k_fin1(const float* __restrict__ rg, const float* __restrict__ rb,
                       const float* __restrict__ pg, const float* __restrict__ pb) {
    int c = blockIdx.x;   // 0..255
    float s = 0.f, q = 0.f;
    if (c < CO) {
        for (int i = threadIdx.x; i < RAWG; i += 128) { s += g_pU[i*CO + c]; q += g_pUQ[i*CO + c]; }
    } else {
        int cc = c - CO;
        for (int i = threadIdx.x; i < GRIDG; i += 128) { s += g_pV[i*CO + cc]; q += g_pVQ[i*CO + cc]; }
    }
    __shared__ float sh[256];
    sh[threadIdx.x] = s; sh[128 + threadIdx.x] = q;
    __syncthreads();
    for (int st = 64; st; st >>= 1) {
        if (threadIdx.x < st) {
            sh[threadIdx.x]       += sh[threadIdx.x + st];
            sh[128 + threadIdx.x] += sh[128 + threadIdx.x + st];
        }
        __syncthreads();
    }
    if (threadIdx.x == 0) {
        float mean = sh[0] / (float)NPTS;
        float var  = sh[128] / (float)NPTS - mean*mean;
        float rstd = rsqrtf(var + 1e-5f);
        float g  = (c < CO) ? rg[c] : pg[c - CO];
        float be = (c < CO) ? rb[c] : pb[c - CO];
        g_sc1[c] = rstd * g;
        g_bi1[c] = be - mean * rstd * g;
    }
}

__global__ void k_fin2(const float* __restrict__ fg, const float* __restrict__ fb) {
    int c = blockIdx.x;   // 0..127
    float s = 0.f, q = 0.f;
    for (int i = threadIdx.x; i < GRIDG; i += 128) { s += g_pF[i*CO + c]; q += g_pFQ[i*CO + c]; }
    __shared__ float sh[256];
    sh[threadIdx.x] = s; sh[128 + threadIdx.x] = q;
    __syncthreads();
    for (int st = 64; st; st >>= 1) {
        if (threadIdx.x < st) {
            sh[threadIdx.x]       += sh[threadIdx.x + st];
            sh[128 + threadIdx.x] += sh[128 + threadIdx.x + st];
        }
        __syncthreads();
    }
    if (threadIdx.x == 0) {
        float mean = sh[0] / (float)NPTS;
        float var  = sh[128] / (float)NPTS - mean*mean;
        float rstd = rsqrtf(var + 1e-5f);
        g_sc2[c] = rstd * fg[c];
        g_bi2[c] = fb[c] - mean * rstd * fg[c];
    }
}

// ---------------- final affine + relu + reshape (float4) ----------------
__global__ void k_out(float* __restrict__ out) {
    int e4 = blockIdx.x * 256 + threadIdx.x;
    int idx = e4 << 2;
    int o = idx / NPTS;
    int p = idx - o * NPTS;
    int t  = p & (TT - 1);
    int bj = p >> 9;
    int j  = bj % JJ;
    int b  = bj / JJ;
    float4 v = *(const float4*)&g_F[idx];
    float sc = g_sc2[o], bi = g_bi2[o];
    v.x = fmaxf(fmaf(v.x, sc, bi), 0.f);
    v.y = fmaxf(fmaf(v.y, sc, bi), 0.f);
    v.z = fmaxf(fmaf(v.z, sc, bi), 0.f);
    v.w = fmaxf(fmaf(v.w, sc, bi), 0.f);
    *(float4*)&out[((b*CO + o)*JJ + j)*TT + t] = v;
}

// ---------------- launcher ----------------
extern "C" void kernel_launch(void* const* d_in, const int* in_sizes, int n_in,
                              void* d_out, int out_size) {
    const float* x      = (const float*)d_in[0];
    const int*   path   = (const int*)  d_in[1];
    const float* raw_w  = (const float*)d_in[2];
    const float* raw_b  = (const float*)d_in[3];
    const float* raw_g  = (const float*)d_in[4];
    const float* raw_be = (const float*)d_in[5];
    const float* ps_w   = (const float*)d_in[6];
    const float* ps_b   = (const float*)d_in[7];
    const float* ps_g   = (const float*)d_in[8];
    const float* ps_be  = (const float*)d_in[9];
    const float* fus_w  = (const float*)d_in[10];
    const float* fus_b  = (const float*)d_in[11];
    const float* fus_g  = (const float*)d_in[12];
    const float* fus_be = (const float*)d_in[13];
    float* out = (float*)d_out;

    cudaFuncSetAttribute(k_gemm_tc, cudaFuncAttributeMaxDynamicSharedMemorySize, SMEM_GEMM);

    k_prep<<<2, 256>>>(ps_w, fus_w);
    k_sig<<<NPTS/256, 256>>>(x, path);
    k_raw<<<RAWG, 256>>>(x, raw_w, raw_b);
    k_gemm_tc<<<GRIDG, 256, SMEM_GEMM>>>(0, ps_b);
    k_fin1<<<2*CO, 128>>>(raw_g, raw_be, ps_g, ps_be);
    k_gemm_tc<<<GRIDG, 256, SMEM_GEMM>>>(1, fus_b);
    k_fin2<<<CO, 128>>>(fus_g, fus_be);
    k_out<<<(CO*NPTS)/1024, 256>>>(out);
}

// round 5
// speedup vs baseline: 2.2692x; 1.1115x over previous
#include <cuda_runtime.h>
#include <cuda_bf16.h>
#include <stdint.h>

#define BB 64
#define CC 3
#define JJ 11
#define TT 512
#define CO 128
#define NPTS (BB*JJ*TT)      /* 360448 = 2816*128 */
#define SIGC 84
#define K1A 168              /* ps actual K */
#define K2A 256              /* fus actual K */
#define NT 128               /* points per GEMM CTA tile */
#define GRIDG (NPTS/NT)      /* 2816 gemm tiles */
#define RAWG (BB*JJ)         /* 704 raw-conv CTAs */
#define KS 32                /* GEMM k-chunk */

// ---------------- static scratch ----------------
__device__ uint32_t g_Spk[K1A * NPTS];       // sig packed (bf16 hi | bf16 lo<<16), [k][p]
__device__ float g_UV[(size_t)K2A * NPTS];   // rows 0..127 = U, 128..255 = V
__device__ float g_F[(size_t)CO * NPTS];     // fus pre-BN, channel-major
__device__ __nv_bfloat16 g_Aps_hi[6*4096],  g_Aps_lo[6*4096];   // [kc32][o][k32]
__device__ __nv_bfloat16 g_Afus_hi[8*4096], g_Afus_lo[8*4096];
__device__ float g_pU[RAWG*CO],   g_pUQ[RAWG*CO];
__device__ float g_pV[GRIDG*CO],  g_pVQ[GRIDG*CO];
__device__ float g_pF[GRIDG*CO],  g_pFQ[GRIDG*CO];
__device__ float g_sc1[K2A], g_bi1[K2A];
__device__ float g_sc2[CO],  g_bi2[CO];

// ---------------- PTX helpers (sm_80-level) ----------------
__device__ __forceinline__ uint32_t smem_u32(const void* p) {
    uint32_t a;
    asm("{ .reg .u64 t; cvta.to.shared.u64 t, %1; cvt.u32.u64 %0, t; }" : "=r"(a) : "l"(p));
    return a;
}
__device__ __forceinline__ void ldsm_x4(uint32_t (&r)[4], uint32_t addr) {
    asm volatile("ldmatrix.sync.aligned.m8n8.x4.shared.b16 {%0,%1,%2,%3}, [%4];"
        : "=r"(r[0]), "=r"(r[1]), "=r"(r[2]), "=r"(r[3]) : "r"(addr));
}
__device__ __forceinline__ void ldsm_x2_t(uint32_t (&r)[2], uint32_t addr) {
    asm volatile("ldmatrix.sync.aligned.m8n8.x2.trans.shared.b16 {%0,%1}, [%2];"
        : "=r"(r[0]), "=r"(r[1]) : "r"(addr));
}
__device__ __forceinline__ void mma_bf16(float (&d)[4], const uint32_t (&a)[4],
                                         const uint32_t (&b)[2]) {
    asm volatile("mma.sync.aligned.m16n8k16.row.col.f32.bf16.bf16.f32 "
        "{%0,%1,%2,%3}, {%4,%5,%6,%7}, {%8,%9}, {%0,%1,%2,%3};"
        : "+f"(d[0]), "+f"(d[1]), "+f"(d[2]), "+f"(d[3])
        : "r"(a[0]), "r"(a[1]), "r"(a[2]), "r"(a[3]), "r"(b[0]), "r"(b[1]));
}
__device__ __forceinline__ void cp16(uint32_t dst, const void* src, uint32_t sz) {
    asm volatile("cp.async.cg.shared.global [%0], [%1], 16, %2;"
        :: "r"(dst), "l"(src), "r"(sz));
}
#define CP_COMMIT() asm volatile("cp.async.commit_group;")
#define CP_WAIT0()  asm volatile("cp.async.wait_group 0;")
#define CP_WAIT1()  asm volatile("cp.async.wait_group 1;")

__device__ __forceinline__ uint32_t pack_hi(float a, float b, uint32_t& lo) {
    __nv_bfloat16 ha = __float2bfloat16(a), hb = __float2bfloat16(b);
    __nv_bfloat16 la = __float2bfloat16(a - __bfloat162float(ha));
    __nv_bfloat16 lb = __float2bfloat16(b - __bfloat162float(hb));
    lo = (uint32_t)__bfloat16_as_ushort(la) | ((uint32_t)__bfloat16_as_ushort(lb) << 16);
    return (uint32_t)__bfloat16_as_ushort(ha) | ((uint32_t)__bfloat16_as_ushort(hb) << 16);
}
__device__ __forceinline__ uint32_t pack1(float v) {
    __nv_bfloat16 h = __float2bfloat16(v);
    __nv_bfloat16 l = __float2bfloat16(v - __bfloat162float(h));
    return (uint32_t)__bfloat16_as_ushort(h) | ((uint32_t)__bfloat16_as_ushort(l) << 16);
}

// SMEM layout (bytes within dynamic smem):
// A: [stage][plane] 128 rows x 40-el stride (80B), data 64B + 16B pad
#define OFF_A(s,pl)  ((s)*20480 + (pl)*10240)
#define OFF_RAW(s)   (40960 + (s)*16384)
// B bf16: [stage][plane] 32 rows x 136-el stride (272B)
#define OFF_B(s,pl)  (73728 + (s)*17408 + (pl)*8704)
#define OFF_SC 108544
#define OFF_BI 109568
#define SMEM_GEMM 110592

// ---------------- depth-3 signature Chen step (c = 4) ----------------
__device__ __forceinline__ void sig_step(float S1[4], float S2[16], float S3[64],
                                         const float d[4]) {
    float dd[16];
#pragma unroll
    for (int i = 0; i < 4; i++)
#pragma unroll
        for (int j = 0; j < 4; j++) dd[i*4+j] = d[i]*d[j];
    float a[4];
#pragma unroll
    for (int i = 0; i < 4; i++) a[i] = 0.5f*S1[i] + d[i]*(1.0f/6.0f);
#pragma unroll
    for (int i = 0; i < 4; i++)
#pragma unroll
        for (int j = 0; j < 4; j++)
#pragma unroll
            for (int k = 0; k < 4; k++)
                S3[i*16+j*4+k] += S2[i*4+j]*d[k] + a[i]*dd[j*4+k];
#pragma unroll
    for (int i = 0; i < 4; i++)
#pragma unroll
        for (int j = 0; j < 4; j++)
            S2[i*4+j] += S1[i]*d[j] + 0.5f*dd[i*4+j];
#pragma unroll
    for (int i = 0; i < 4; i++) S1[i] += d[i];
}

__device__ __forceinline__ void sig_write(int rowbase, int p,
                                          const float S1[4], const float S2[16],
                                          const float S3[64]) {
#pragma unroll
    for (int i = 0; i < 4; i++)  g_Spk[(rowbase + i)      * NPTS + p] = pack1(S1[i]);
#pragma unroll
    for (int i = 0; i < 16; i++) g_Spk[(rowbase + 4 + i)  * NPTS + p] = pack1(S2[i]);
#pragma unroll
    for (int i = 0; i < 64; i++) g_Spk[(rowbase + 20 + i) * NPTS + p] = pack1(S3[i]);
}

// ---------------- K1: signatures ----------------
__global__ void k_sig(const float* __restrict__ x, const int* __restrict__ path) {
    int p = blockIdx.x * blockDim.x + threadIdx.x;
    if (p >= NPTS) return;
    int t  = p & (TT - 1);
    int bj = p >> 9;
    int j  = bj % JJ;
    int b  = bj / JJ;
    const float* xb = x + (size_t)b * CC * JJ * TT;

    float S1[4], S2[16], S3[64];
    float prev[3], cur[3], d[4];

#pragma unroll
    for (int i = 0; i < 4; i++)  S1[i] = 0.f;
#pragma unroll
    for (int i = 0; i < 16; i++) S2[i] = 0.f;
#pragma unroll
    for (int i = 0; i < 64; i++) S3[i] = 0.f;

    int j0 = path[j*3+0], j1 = path[j*3+1], j2 = path[j*3+2];
#pragma unroll
    for (int c = 0; c < 3; c++) prev[c] = xb[(c*JJ + j0)*TT + t];
    d[0] = 0.f; d[1] = prev[0]; d[2] = prev[1]; d[3] = prev[2];
    sig_step(S1, S2, S3, d);
#pragma unroll
    for (int c = 0; c < 3; c++) cur[c] = xb[(c*JJ + j1)*TT + t];
    d[0] = 0.5f;
#pragma unroll
    for (int c = 0; c < 3; c++) { d[c+1] = cur[c] - prev[c]; prev[c] = cur[c]; }
    sig_step(S1, S2, S3, d);
#pragma unroll
    for (int c = 0; c < 3; c++) cur[c] = xb[(c*JJ + j2)*TT + t];
    d[0] = 0.5f;
#pragma unroll
    for (int c = 0; c < 3; c++) d[c+1] = cur[c] - prev[c];
    sig_step(S1, S2, S3, d);
    sig_write(0, p, S1, S2, S3);

#pragma unroll
    for (int i = 0; i < 4; i++)  S1[i] = 0.f;
#pragma unroll
    for (int i = 0; i < 16; i++) S2[i] = 0.f;
#pragma unroll
    for (int i = 0; i < 64; i++) S3[i] = 0.f;

#pragma unroll
    for (int l = 0; l < 7; l++) {
        int tc = t + l - 3;
        tc = tc < 0 ? 0 : (tc > TT-1 ? TT-1 : tc);
#pragma unroll
        for (int c = 0; c < 3; c++) cur[c] = xb[(c*JJ + j)*TT + tc];
        if (l == 0) {
            d[0] = 0.f;
#pragma unroll
            for (int c = 0; c < 3; c++) d[c+1] = cur[c];
        } else {
            d[0] = 1.0f/6.0f;
#pragma unroll
            for (int c = 0; c < 3; c++) d[c+1] = cur[c] - prev[c];
        }
#pragma unroll
        for (int c = 0; c < 3; c++) prev[c] = cur[c];
        sig_step(S1, S2, S3, d);
    }
    sig_write(SIGC, p, S1, S2, S3);
}

// ---------------- K2: raw conv + bias + fused BN partials ----------------
__global__ void k_raw(const float* __restrict__ x, const float* __restrict__ w,
                      const float* __restrict__ b) {
    __shared__ float xs[3][TT + 2];
    __shared__ float ws[CO * 9];
    __shared__ float bs[CO];
    int bj = blockIdx.x;
    int j = bj % JJ, bb = bj / JJ;
    int tid = threadIdx.x;
    int warp = tid >> 5, lane = tid & 31;

    for (int i = tid; i < 3*(TT+2); i += 256) {
        int c = i / (TT+2), tt = i % (TT+2);
        xs[c][tt] = (tt >= 1 && tt <= TT) ? x[((bb*3 + c)*JJ + j)*TT + tt - 1] : 0.f;
    }
    for (int i = tid; i < CO*9; i += 256) ws[i] = w[i];
    if (tid < CO) bs[tid] = b[tid];
    __syncthreads();

    int pbase = bj * TT;
#pragma unroll 1
    for (int oi = 0; oi < 16; oi++) {
        int o = warp*16 + oi;
        float wr[9];
#pragma unroll
        for (int i = 0; i < 9; i++) wr[i] = ws[o*9 + i];
        float bo = bs[o];
        float s = 0.f, q = 0.f;
        float* orow = g_UV + (size_t)o*NPTS + pbase;
#pragma unroll
        for (int i = 0; i < 16; i++) {
            int t = i*32 + lane;
            float a = bo;
#pragma unroll
            for (int c = 0; c < 3; c++)
#pragma unroll
                for (int kw = 0; kw < 3; kw++)
                    a = fmaf(xs[c][t + kw], wr[c*3 + kw], a);
            orow[t] = a;
            s += a; q += a*a;
        }
#pragma unroll
        for (int d = 16; d; d >>= 1) {
            s += __shfl_xor_sync(0xffffffffu, s, d);
            q += __shfl_xor_sync(0xffffffffu, q, d);
        }
        if (lane == 0) { g_pU[bj*CO + o] = s; g_pUQ[bj*CO + o] = q; }
    }
}

// ---------------- prep: bf16 hi/lo weight images, [kc32][o][k32] ----------------
__global__ void k_prep(const float* __restrict__ psw, const float* __restrict__ fusw) {
    int which = blockIdx.x;
    const float* W = which ? fusw : psw;
    int K  = which ? 256 : 168;
    int KP = which ? 256 : 192;
    __nv_bfloat16* AH = which ? g_Afus_hi : g_Aps_hi;
    __nv_bfloat16* AL = which ? g_Afus_lo : g_Aps_lo;
    for (int idx = threadIdx.x; idx < 128*KP; idx += blockDim.x) {
        int o = idx / KP, k = idx % KP;
        float v = (k < K) ? W[o*K + k] : 0.f;
        __nv_bfloat16 h = __float2bfloat16(v);
        __nv_bfloat16 l = __float2bfloat16(v - __bfloat162float(h));
        int kc = k >> 5, kk = k & 31;
        AH[kc*4096 + o*32 + kk] = h;
        AL[kc*4096 + o*32 + kk] = l;
    }
}

// ---------------- pipelined tensor-core GEMM: D[128ch][128pts]/CTA ----------------
__device__ __forceinline__ void issue_chunk(int c, int tid, uint32_t sb,
        const __nv_bfloat16* __restrict__ Ahg, const __nv_bfloat16* __restrict__ Alg,
        const char* __restrict__ Bg, int kact, int p0) {
    int s = c & 1;
    // A: 2 planes x 512 x 16B
#pragma unroll
    for (int i = 0; i < 4; i++) {
        int m = tid + i*256;
        int plane = m >> 9, mm = m & 511;
        int o = mm >> 2, kq = mm & 3;
        const __nv_bfloat16* src = (plane ? Alg : Ahg) + c*4096 + o*32 + kq*8;
        cp16(sb + OFF_A(s, plane) + o*80 + kq*16, src, 16);
    }
    // B raw: 1024 x 16B, linear [k32][p128]
#pragma unroll
    for (int i = 0; i < 4; i++) {
        int m = tid + i*256;
        int kl = m >> 5, pseg = m & 31;
        int kg = c*KS + kl;
        int ok = kg < kact;
        int kgc = ok ? kg : 0;
        const char* src = Bg + ((size_t)kgc*NPTS + p0 + pseg*4)*4;
        cp16(sb + OFF_RAW(s) + m*16, src, ok ? 16u : 0u);
    }
}

__global__ void __launch_bounds__(256, 2) k_gemm_tc(int mode, const float* __restrict__ bias) {
    extern __shared__ char smc[];
    __shared__ float sS[CO], sQ[CO];
    uint32_t sb = smem_u32(smc);
    float* s_sc = (float*)(smc + OFF_SC);
    float* s_bi = (float*)(smc + OFF_BI);

    int tid = threadIdx.x;
    int warp = tid >> 5, lane = tid & 31;
    int wm = (warp >> 2) * 64;
    int wn = (warp & 3) * 32;
    int p0 = blockIdx.x * NT;

    int kact, kchunks;
    const __nv_bfloat16 *Ahg, *Alg;
    const char* Bg;
    float *Out, *pS, *pQ;
    if (mode == 0) {
        kact = K1A; kchunks = 6;
        Ahg = g_Aps_hi; Alg = g_Aps_lo; Bg = (const char*)g_Spk;
        Out = g_UV + (size_t)CO*NPTS; pS = g_pV; pQ = g_pVQ;
    } else {
        kact = K2A; kchunks = 8;
        Ahg = g_Afus_hi; Alg = g_Afus_lo; Bg = (const char*)g_UV;
        Out = g_F; pS = g_pF; pQ = g_pFQ;
    }

    if (mode)
        for (int i = tid; i < K2A; i += 256) { s_sc[i] = g_sc1[i]; s_bi[i] = g_bi1[i]; }
    if (tid < CO) { sS[tid] = 0.f; sQ[tid] = 0.f; }

    float acc[4][4][4];
#pragma unroll
    for (int i = 0; i < 4; i++)
#pragma unroll
        for (int j = 0; j < 4; j++)
#pragma unroll
            for (int r = 0; r < 4; r++) acc[i][j][r] = 0.f;

    // prologue: prefetch chunks 0 and 1, convert 0
    issue_chunk(0, tid, sb, Ahg, Alg, Bg, kact, p0); CP_COMMIT();
    issue_chunk(1, tid, sb, Ahg, Alg, Bg, kact, p0); CP_COMMIT();
    CP_WAIT1();
    __syncthreads();
    // convert chunk 0
    {
        const char* raw = smc + OFF_RAW(0);
        __nv_bfloat16* bh = (__nv_bfloat16*)(smc + OFF_B(0,0));
        __nv_bfloat16* bl = (__nv_bfloat16*)(smc + OFF_B(0,1));
#pragma unroll
        for (int g = 0; g < 4; g++) {
            int m = tid + g*256;
            int kl = m >> 5, l4 = (m & 31) * 4;
            uint2 h, l;
            if (mode) {
                float4 v = *(const float4*)(raw + m*16);
                float sc = s_sc[kl], bi = s_bi[kl];
                v.x = fmaxf(fmaf(v.x, sc, bi), 0.f);
                v.y = fmaxf(fmaf(v.y, sc, bi), 0.f);
                v.z = fmaxf(fmaf(v.z, sc, bi), 0.f);
                v.w = fmaxf(fmaf(v.w, sc, bi), 0.f);
                h.x = pack_hi(v.x, v.y, l.x);
                h.y = pack_hi(v.z, v.w, l.y);
            } else {
                uint4 v = *(const uint4*)(raw + m*16);
                h.x = __byte_perm(v.x, v.y, 0x5410); l.x = __byte_perm(v.x, v.y, 0x7632);
                h.y = __byte_perm(v.z, v.w, 0x5410); l.y = __byte_perm(v.z, v.w, 0x7632);
            }
            *(uint2*)(bh + kl*136 + l4) = h;
            *(uint2*)(bl + kl*136 + l4) = l;
        }
    }
    __syncthreads();

    for (int c = 0; c < kchunks; c++) {
        int s = c & 1;
        // ---- MMA on chunk c ----
#pragma unroll
        for (int ks = 0; ks < 2; ks++) {
            int k0 = ks * 16;
            uint32_t ah[4][4], al[4][4];
#pragma unroll
            for (int i = 0; i < 4; i++) {
                uint32_t off = (uint32_t)((wm + i*16 + (lane & 15))*80
                                        + k0*2 + (lane >> 4)*16);
                ldsm_x4(ah[i], sb + OFF_A(s,0) + off);
                ldsm_x4(al[i], sb + OFF_A(s,1) + off);
            }
#pragma unroll
            for (int j = 0; j < 4; j++) {
                uint32_t bh[2], bl[2];
                uint32_t boff = (uint32_t)((k0 + (lane & 15))*272 + (wn + j*8)*2);
                ldsm_x2_t(bh, sb + OFF_B(s,0) + boff);
                ldsm_x2_t(bl, sb + OFF_B(s,1) + boff);
#pragma unroll
                for (int i = 0; i < 4; i++) {
                    mma_bf16(acc[i][j], ah[i], bh);
                    mma_bf16(acc[i][j], ah[i], bl);
                    mma_bf16(acc[i][j], al[i], bh);
                }
            }
        }
        // ---- pipeline bookkeeping ----
        if (c + 1 < kchunks) {
            CP_WAIT0();            // chunk c+1 fully arrived
            __syncthreads();       // all MMA(c) reads done; cp.asyncs visible
            if (c + 2 < kchunks) { issue_chunk(c+2, tid, sb, Ahg, Alg, Bg, kact, p0); CP_COMMIT(); }
            // convert chunk c+1
            int s1 = (c + 1) & 1;
            const char* raw = smc + OFF_RAW(s1);
            __nv_bfloat16* bh = (__nv_bfloat16*)(smc + OFF_B(s1,0));
            __nv_bfloat16* bl = (__nv_bfloat16*)(smc + OFF_B(s1,1));
#pragma unroll
            for (int g = 0; g < 4; g++) {
                int m = tid + g*256;
                int kl = m >> 5, l4 = (m & 31) * 4;
                uint2 h, l;
                if (mode) {
                    float4 v = *(const float4*)(raw + m*16);
                    int kg = (c+1)*KS + kl;
                    float sc = s_sc[kg], bi = s_bi[kg];
                    v.x = fmaxf(fmaf(v.x, sc, bi), 0.f);
                    v.y = fmaxf(fmaf(v.y, sc, bi), 0.f);
                    v.z = fmaxf(fmaf(v.z, sc, bi), 0.f);
                    v.w = fmaxf(fmaf(v.w, sc, bi), 0.f);
                    h.x = pack_hi(v.x, v.y, l.x);
                    h.y = pack_hi(v.z, v.w, l.y);
                } else {
                    uint4 v = *(const uint4*)(raw + m*16);
                    h.x = __byte_perm(v.x, v.y, 0x5410); l.x = __byte_perm(v.x, v.y, 0x7632);
                    h.y = __byte_perm(v.z, v.w, 0x5410); l.y = __byte_perm(v.z, v.w, 0x7632);
                }
                *(uint2*)(bh + kl*136 + l4) = h;
                *(uint2*)(bl + kl*136 + l4) = l;
            }
            __syncthreads();
        }
    }

    // ---- epilogue: bias, store channel-major, fused BN partials ----
#pragma unroll
    for (int i = 0; i < 4; i++) {
        int c0 = wm + i*16 + (lane >> 2);
        int c1 = c0 + 8;
        float b0 = bias[c0], b1 = bias[c1];
        float s0 = 0.f, q0 = 0.f, s1 = 0.f, q1 = 0.f;
#pragma unroll
        for (int j = 0; j < 4; j++) {
            float v00 = acc[i][j][0] + b0, v01 = acc[i][j][1] + b0;
            float v10 = acc[i][j][2] + b1, v11 = acc[i][j][3] + b1;
            int p = p0 + wn + j*8 + ((lane & 3) << 1);
            *(float2*)&Out[(size_t)c0*NPTS + p] = make_float2(v00, v01);
            *(float2*)&Out[(size_t)c1*NPTS + p] = make_float2(v10, v11);
            s0 += v00 + v01; q0 += v00*v00 + v01*v01;
            s1 += v10 + v11; q1 += v10*v10 + v11*v11;
        }
#pragma unroll
        for (int d = 1; d < 4; d <<= 1) {
            s0 += __shfl_xor_sync(0xffffffffu, s0, d);
            q0 += __shfl_xor_sync(0xffffffffu, q0, d);
            s1 += __shfl_xor_sync(0xffffffffu, s1, d);
            q1 += __shfl_xor_sync(0xffffffffu, q1, d);
        }
        if ((lane & 3) == 0) {
            atomicAdd(&sS[c0], s0); atomicAdd(&sQ[c0], q0);
            atomicAdd(&sS[c1], s1); atomicAdd(&sQ[c1], q1);
        }
    }
    __syncthreads();
    if (tid < CO) {
        pS[blockIdx.x*CO + tid] = sS[tid];
        pQ[blockIdx.x*CO + tid] = sQ[tid];
    }
}

// ---------------- finalize BN affines ----------------
__global__ void k_fin1(const float* __restrict__ rg, const float* __restrict__ rb,
                       const float* __restrict__ pg, const float* __restrict__ pb) {
    int c = blockIdx.x;   // 0..255
    float s = 0.f, q = 0.f;
    if (c < CO) {
        for (int i = threadIdx.x; i < RAWG; i += 128) { s += g_pU[i*CO + c]; q += g_pUQ[i*CO + c]; }
    } else {
        int cc = c - CO;
        for (int i = threadIdx.x; i < GRIDG; i += 128) { s += g_pV[i*CO + cc]; q += g_pVQ[i*CO + cc]; }
    }
    __shared__ float sh[256];
    sh[threadIdx.x] = s; sh[128 + threadIdx.x] = q;
    __syncthreads();
    for (int st = 64; st; st >>= 1) {
        if (threadIdx.x < st) {
            sh[threadIdx.x]       += sh[threadIdx.x + st];
            sh[128 + threadIdx.x] += sh[128 + threadIdx.x + st];
        }
        __syncthreads();
    }
    if (threadIdx.x == 0) {
        float mean = sh[0] / (float)NPTS;
        float var  = sh[128] / (float)NPTS - mean*mean;
        float rstd = rsqrtf(var + 1e-5f);
        float g  = (c < CO) ? rg[c] : pg[c - CO];
        float be = (c < CO) ? rb[c] : pb[c - CO];
        g_sc1[c] = rstd * g;
        g_bi1[c] = be - mean * rstd * g;
    }
}

__global__ void k_fin2(const float* __restrict__ fg, const float* __restrict__ fb) {
    int c = blockIdx.x;   // 0..127
    float s = 0.f, q = 0.f;
    for (int i = threadIdx.x; i < GRIDG; i += 128) { s += g_pF[i*CO + c]; q += g_pFQ[i*CO + c]; }
    __shared__ float sh[256];
    sh[threadIdx.x] = s; sh[128 + threadIdx.x] = q;
    __syncthreads();
    for (int st = 64; st; st >>= 1) {
        if (threadIdx.x < st) {
            sh[threadIdx.x]       += sh[threadIdx.x + st];
            sh[128 + threadIdx.x] += sh[128 + threadIdx.x + st];
        }
        __syncthreads();
    }
    if (threadIdx.x == 0) {
        float mean = sh[0] / (float)NPTS;
        float var  = sh[128] / (float)NPTS - mean*mean;
        float rstd = rsqrtf(var + 1e-5f);
        g_sc2[c] = rstd * fg[c];
        g_bi2[c] = fb[c] - mean * rstd * fg[c];
    }
}

// ---------------- final affine + relu + reshape (float4) ----------------
__global__ void k_out(float* __restrict__ out) {
    int e4 = blockIdx.x * 256 + threadIdx.x;
    int idx = e4 << 2;
    int o = idx / NPTS;
    int p = idx - o * NPTS;
    int t  = p & (TT - 1);
    int bj = p >> 9;
    int j  = bj % JJ;
    int b  = bj / JJ;
    float4 v = *(const float4*)&g_F[idx];
    float sc = g_sc2[o], bi = g_bi2[o];
    v.x = fmaxf(fmaf(v.x, sc, bi), 0.f);
    v.y = fmaxf(fmaf(v.y, sc, bi), 0.f);
    v.z = fmaxf(fmaf(v.z, sc, bi), 0.f);
    v.w = fmaxf(fmaf(v.w, sc, bi), 0.f);
    *(float4*)&out[((b*CO + o)*JJ + j)*TT + t] = v;
}

// ---------------- launcher ----------------
extern "C" void kernel_launch(void* const* d_in, const int* in_sizes, int n_in,
                              void* d_out, int out_size) {
    const float* x      = (const float*)d_in[0];
    const int*   path   = (const int*)  d_in[1];
    const float* raw_w  = (const float*)d_in[2];
    const float* raw_b  = (const float*)d_in[3];
    const float* raw_g  = (const float*)d_in[4];
    const float* raw_be = (const float*)d_in[5];
    const float* ps_w   = (const float*)d_in[6];
    const float* ps_b   = (const float*)d_in[7];
    const float* ps_g   = (const float*)d_in[8];
    const float* ps_be  = (const float*)d_in[9];
    const float* fus_w  = (const float*)d_in[10];
    const float* fus_b  = (const float*)d_in[11];
    const float* fus_g  = (const float*)d_in[12];
    const float* fus_be = (const float*)d_in[13];
    float* out = (float*)d_out;

    cudaFuncSetAttribute(k_gemm_tc, cudaFuncAttributeMaxDynamicSharedMemorySize, SMEM_GEMM);

    k_prep<<<2, 256>>>(ps_w, fus_w);
    k_sig<<<NPTS/256, 256>>>(x, path);
    k_raw<<<RAWG, 256>>>(x, raw_w, raw_b);
    k_gemm_tc<<<GRIDG, 256, SMEM_GEMM>>>(0, ps_b);
    k_fin1<<<2*CO, 128>>>(raw_g, raw_be, ps_g, ps_be);
    k_gemm_tc<<<GRIDG, 256, SMEM_GEMM>>>(1, fus_b);
    k_fin2<<<CO, 128>>>(fus_g, fus_be);
    k_out<<<(CO*NPTS)/1024, 256>>>(out);
}